// round 1
// baseline (speedup 1.0000x reference)
#include <cuda_runtime.h>
#include <cstdint>
#include <cstddef>
#include <math_constants.h>

// ---------------------------------------------------------------------------
// JointNet: DGCNN geo-net (3 dynamic-kNN edge convs) + weighted joint pooling
//           + skeleton edge convs (fixed one-ring) + joint MLP.
// Key rewrite: edge conv  max_k leaky(w1*(xj-xi) + w2*xi + b)
//            = leaky( Q[i] + max_k P[idx[i,k]] ),  P = X*w1^T, Q = X*(w2-w1)^T + b
// ---------------------------------------------------------------------------

static constexpr int Bb = 4, Nn = 4096, Jj = 24, KTOP = 20;

#define LRELU(x) ((x) >= 0.f ? (x) : 0.2f * (x))

// ------------------------- scratch (floats) --------------------------------
static constexpr size_t OF_FEAT = 0;                       // [4][4096][451]
static constexpr size_t SZ_FEAT = (size_t)Bb * Nn * 451;
static constexpr size_t OF_PQ   = OF_FEAT + SZ_FEAT;       // [4*4096][512] max
static constexpr size_t SZ_PQ   = (size_t)Bb * Nn * 512;
static constexpr size_t OF_NORM = OF_PQ + SZ_PQ;           // [4*4096]
static constexpr size_t SZ_NORM = (size_t)Bb * Nn;
static constexpr size_t OF_POOL = OF_NORM + SZ_NORM;       // [96][451]
static constexpr size_t SZ_POOL = (size_t)Bb * Jj * 451;
static constexpr size_t OF_JNT  = OF_POOL + SZ_POOL;       // [96][448]
static constexpr size_t SZ_JNT  = (size_t)Bb * Jj * 448;
static constexpr size_t OF_T1   = OF_JNT + SZ_JNT;         // [96][512]
static constexpr size_t SZ_T1   = (size_t)Bb * Jj * 512;
static constexpr size_t OF_T2   = OF_T1 + SZ_T1;           // [96][256]
static constexpr size_t SZ_T2   = (size_t)Bb * Jj * 256;
static constexpr size_t OF_WG1  = OF_T2 + SZ_T2;   static constexpr size_t SZ_WG1 = 2 * 64 * 3;
static constexpr size_t OF_WG2  = OF_WG1 + SZ_WG1; static constexpr size_t SZ_WG2 = 2 * 128 * 64;
static constexpr size_t OF_WG3  = OF_WG2 + SZ_WG2; static constexpr size_t SZ_WG3 = 2 * 256 * 128;
static constexpr size_t OF_WS1  = OF_WG3 + SZ_WG3; static constexpr size_t SZ_WS1 = 2 * 256 * 451;
static constexpr size_t OF_WS2  = OF_WS1 + SZ_WS1; static constexpr size_t SZ_WS2 = 2 * 128 * 256;
static constexpr size_t OF_WS3  = OF_WS2 + SZ_WS2; static constexpr size_t SZ_WS3 = 2 * 64 * 128;
static constexpr size_t SF_TOTAL = OF_WS3 + SZ_WS3;

__device__ float d_SF[SF_TOTAL];
__device__ int   d_SI[(size_t)Bb * Nn * KTOP];

// ------------------------- wc prep: wc[o]=w1, wc[O+o]=w2-w1 ---------------
__global__ void prep_wc_kernel(const float* __restrict__ w, float* __restrict__ wc,
                               int O, int C) {
    int i = blockIdx.x * blockDim.x + threadIdx.x;
    if (i >= O * C) return;
    int o = i / C, c = i - o * C;
    float w1 = w[(size_t)o * 2 * C + c];
    float w2 = w[(size_t)o * 2 * C + C + c];
    wc[(size_t)o * C + c]       = w1;
    wc[(size_t)(O + o) * C + c] = w2 - w1;
}

// ------------------------- squared norms (warp per row) --------------------
__global__ void norms_kernel(const float* __restrict__ X, int ldx, int C,
                             float* __restrict__ out, int M) {
    int w = (blockIdx.x * blockDim.x + threadIdx.x) >> 5;
    int lane = threadIdx.x & 31;
    if (w >= M) return;
    const float* row = X + (size_t)w * ldx;
    float s = 0.f;
    for (int c = lane; c < C; c += 32) { float v = row[c]; s += v * v; }
    #pragma unroll
    for (int off = 16; off; off >>= 1) s += __shfl_xor_sync(0xffffffffu, s, off);
    if (!lane) out[w] = s;
}

// ------------------------- fused kNN (exact top-20) ------------------------
// Block: 64 queries; streams candidate tiles of 256; 8x8 register microtile
// GEMM for dot products; dist tile staged in smem; 4 threads/query keep
// private sorted top-20 (tie-break: smaller index), 4-way merge at the end.
template<int C>
__global__ __launch_bounds__(256, 2)
void knn_kernel(const float* __restrict__ X, int ldx,
                const float* __restrict__ norms, int* __restrict__ out_idx) {
    constexpr int KC = (C < 16) ? C : 16;
    constexpr int QT = 64, CT = 256;
    constexpr int CPAD = 260, QPAD = 68, DPAD = 260;

    extern __shared__ float sm[];
    float* cs = sm;                       // [KC][CPAD]
    float* qs = cs + KC * CPAD;           // [KC][QPAD]
    float* dt = qs + KC * QPAD;           // [QT][DPAD]
    float* cn = dt + QT * DPAD;           // [CT]
    float* qn = cn + CT;                  // [QT]

    const int t  = threadIdx.x;
    const int tx = t & 31, ty = t >> 5;
    const int b  = blockIdx.y;
    const int q0 = blockIdx.x * QT;
    const float* Xb = X + (size_t)b * Nn * ldx;
    const float* nb = norms + (size_t)b * Nn;

    if (t < QT) qn[t] = nb[q0 + t];

    float ld[KTOP]; int li[KTOP];
    #pragma unroll
    for (int s = 0; s < KTOP; ++s) { ld[s] = CUDART_INF_F; li[s] = 0x7fffffff; }

    for (int jb = 0; jb < Nn; jb += CT) {
        cn[t] = nb[jb + t];               // CT == blockDim

        float acc[8][8];
        #pragma unroll
        for (int v = 0; v < 8; ++v)
            #pragma unroll
            for (int u = 0; u < 8; ++u) acc[v][u] = 0.f;

        for (int k0 = 0; k0 < C; k0 += KC) {
            __syncthreads();
            for (int e = t; e < CT * KC; e += 256) {
                int row = e / KC, kk = e - row * KC;
                cs[kk * CPAD + row] = Xb[(size_t)(jb + row) * ldx + (k0 + kk)];
            }
            for (int e = t; e < QT * KC; e += 256) {
                int row = e / KC, kk = e - row * KC;
                qs[kk * QPAD + row] = Xb[(size_t)(q0 + row) * ldx + (k0 + kk)];
            }
            __syncthreads();
            #pragma unroll
            for (int kk = 0; kk < KC; ++kk) {
                float4 q1 = *(const float4*)(qs + kk * QPAD + ty * 8);
                float4 q2 = *(const float4*)(qs + kk * QPAD + ty * 8 + 4);
                float4 c1 = *(const float4*)(cs + kk * CPAD + tx * 8);
                float4 c2 = *(const float4*)(cs + kk * CPAD + tx * 8 + 4);
                float qv[8] = {q1.x, q1.y, q1.z, q1.w, q2.x, q2.y, q2.z, q2.w};
                float cv[8] = {c1.x, c1.y, c1.z, c1.w, c2.x, c2.y, c2.z, c2.w};
                #pragma unroll
                for (int v = 0; v < 8; ++v)
                    #pragma unroll
                    for (int u = 0; u < 8; ++u)
                        acc[v][u] = fmaf(qv[v], cv[u], acc[v][u]);
            }
        }
        // distances -> smem tile
        #pragma unroll
        for (int v = 0; v < 8; ++v) {
            int q = ty * 8 + v;
            float qnv = qn[q];
            #pragma unroll
            for (int u = 0; u < 8; ++u) {
                int c = tx * 8 + u;
                dt[q * DPAD + c] = (qnv + cn[c]) - 2.0f * acc[v][u];
            }
        }
        __syncthreads();
        // top-k scan: 4 threads per query, interleaved columns
        {
            int q = t >> 2, sub = t & 3;
            const float* drow = dt + q * DPAD;
            for (int i = 0; i < CT / 4; ++i) {
                int col = sub + 4 * i;
                float d = drow[col];
                int j = jb + col;
                if (d < ld[KTOP - 1] || (d == ld[KTOP - 1] && j < li[KTOP - 1])) {
                    ld[KTOP - 1] = d; li[KTOP - 1] = j;
                    #pragma unroll
                    for (int s = KTOP - 1; s > 0; --s) {
                        bool sw = (ld[s] < ld[s - 1]) ||
                                  (ld[s] == ld[s - 1] && li[s] < li[s - 1]);
                        if (sw) {
                            float td = ld[s]; ld[s] = ld[s - 1]; ld[s - 1] = td;
                            int ti = li[s]; li[s] = li[s - 1]; li[s - 1] = ti;
                        }
                    }
                }
            }
        }
        __syncthreads();
    }

    // merge 4 sorted lists per query (reuse dt region)
    float* md = dt;                       // [QT][4*KTOP]
    int*   mi = (int*)(dt + QT * 4 * KTOP);
    {
        int q = t >> 2, sub = t & 3;
        #pragma unroll
        for (int s = 0; s < KTOP; ++s) {
            md[(q * 4 + sub) * KTOP + s] = ld[s];
            mi[(q * 4 + sub) * KTOP + s] = li[s];
        }
    }
    __syncthreads();
    if (t < QT) {
        int p[4] = {0, 0, 0, 0};
        int* op = out_idx + ((size_t)(b * Nn + q0 + t)) * KTOP;
        for (int kk = 0; kk < KTOP; ++kk) {
            float bd = CUDART_INF_F; int bi = 0x7fffffff; int bs = 0;
            #pragma unroll
            for (int s = 0; s < 4; ++s) {
                if (p[s] < KTOP) {
                    float d = md[(t * 4 + s) * KTOP + p[s]];
                    int  i2 = mi[(t * 4 + s) * KTOP + p[s]];
                    if (d < bd || (d == bd && i2 < bi)) { bd = d; bi = i2; bs = s; }
                }
            }
            #pragma unroll
            for (int s = 0; s < 4; ++s) if (bs == s) p[s]++;
            op[kk] = bi;
        }
    }
}

// ------------------------- generic tiled GEMM: Y = X * Wt^T ----------------
// Wt is [N2][K]; bias added for columns n >= biasFrom as bias[n-biasFrom].
__global__ __launch_bounds__(256)
void gemm_kernel(const float* __restrict__ X, int ldx,
                 const float* __restrict__ Wt,
                 const float* __restrict__ bias, int biasFrom,
                 float* __restrict__ Y, int ldy,
                 int M, int N2, int K, int leaky) {
    constexpr int BM = 64, BN = 64, KC = 16;
    __shared__ float Xs[KC][BM + 1];
    __shared__ float Ws[KC][BN + 1];
    int t = threadIdx.x;
    int tx = t & 15, ty = t >> 4;
    int m0 = blockIdx.x * BM, n0 = blockIdx.y * BN;
    float acc[4][4];
    #pragma unroll
    for (int v = 0; v < 4; ++v)
        #pragma unroll
        for (int u = 0; u < 4; ++u) acc[v][u] = 0.f;

    for (int k0 = 0; k0 < K; k0 += KC) {
        __syncthreads();
        for (int e = t; e < BM * KC; e += 256) {
            int mi_ = e >> 4, kk = e & 15;
            int m = m0 + mi_, k = k0 + kk;
            Xs[kk][mi_] = (m < M && k < K) ? X[(size_t)m * ldx + k] : 0.f;
        }
        for (int e = t; e < BN * KC; e += 256) {
            int ni = e >> 4, kk = e & 15;
            int n = n0 + ni, k = k0 + kk;
            Ws[kk][ni] = (n < N2 && k < K) ? Wt[(size_t)n * K + k] : 0.f;
        }
        __syncthreads();
        #pragma unroll
        for (int kk = 0; kk < KC; ++kk) {
            float xv[4], wv[4];
            #pragma unroll
            for (int v = 0; v < 4; ++v) xv[v] = Xs[kk][ty + 16 * v];
            #pragma unroll
            for (int u = 0; u < 4; ++u) wv[u] = Ws[kk][tx + 16 * u];
            #pragma unroll
            for (int v = 0; v < 4; ++v)
                #pragma unroll
                for (int u = 0; u < 4; ++u)
                    acc[v][u] = fmaf(xv[v], wv[u], acc[v][u]);
        }
    }
    #pragma unroll
    for (int v = 0; v < 4; ++v) {
        int m = m0 + ty + 16 * v;
        if (m >= M) continue;
        #pragma unroll
        for (int u = 0; u < 4; ++u) {
            int n = n0 + tx + 16 * u;
            if (n >= N2) continue;
            float val = acc[v][u];
            if (n >= biasFrom) val += bias[n - biasFrom];
            if (leaky) val = LRELU(val);
            Y[(size_t)m * ldy + n] = val;
        }
    }
}

// ------------------------- gather + max + leaky ----------------------------
// out[row][o] = leaky( Q[row][o] + max_k P[idx[row][k]][o] )
__global__ void gathermax_kernel(const float* __restrict__ PQ, int O,
                                 const int* __restrict__ idx, int k, int nPer,
                                 float* __restrict__ out, int ldo) {
    int row = blockIdx.x;
    int b = row / nPer;
    __shared__ int sidx[32];
    if (threadIdx.x < k) sidx[threadIdx.x] = idx[(size_t)row * k + threadIdx.x];
    __syncthreads();
    int ld2 = 2 * O;
    const float* Pb = PQ + (size_t)b * nPer * ld2;
    const float* Qr = PQ + (size_t)row * ld2 + O;
    float* orow = out + (size_t)row * ldo;
    for (int o = threadIdx.x; o < O; o += blockDim.x) {
        float m = -CUDART_INF_F;
        for (int kk = 0; kk < k; ++kk)
            m = fmaxf(m, Pb[(size_t)sidx[kk] * ld2 + o]);
        float v = m + Qr[o];
        orow[o] = LRELU(v);
    }
}

// ------------------------- copy V into feat[:, :, 0:3] ---------------------
__global__ void copyV_kernel(const float* __restrict__ V, float* __restrict__ feat) {
    int g = blockIdx.x * blockDim.x + threadIdx.x;
    if (g < Bb * Nn * 3) feat[(size_t)(g / 3) * 451 + (g % 3)] = V[g];
}

// ------------------------- weighted pooling onto joints --------------------
// pooled[b][j][c] = sum_n W[b][j][n] feat[b][n][c] / (sum_n W[b][j][n] + 1e-5)
__global__ __launch_bounds__(256)
void pool_kernel(const float* __restrict__ W, const float* __restrict__ feat,
                 float* __restrict__ pooled) {
    __shared__ float Ws_[24][64];
    __shared__ float swj[24];
    int t = threadIdx.x;
    int b = blockIdx.y;
    int cl = t & 63, jg = t >> 6;           // 4 groups x 6 joints
    int c = blockIdx.x * 64 + cl;
    float acc[6] = {0, 0, 0, 0, 0, 0};
    float wsum[6] = {0, 0, 0, 0, 0, 0};
    const float* Wb = W + (size_t)b * Jj * Nn;
    const float* fb = feat + (size_t)b * Nn * 451;
    for (int n0 = 0; n0 < Nn; n0 += 64) {
        __syncthreads();
        for (int e = t; e < 24 * 64; e += 256) {
            int j = e >> 6, nn = e & 63;
            Ws_[j][nn] = Wb[(size_t)j * Nn + n0 + nn];
        }
        __syncthreads();
        for (int nn = 0; nn < 64; ++nn) {
            float f = (c < 451) ? fb[(size_t)(n0 + nn) * 451 + c] : 0.f;
            #pragma unroll
            for (int jj = 0; jj < 6; ++jj) {
                float wv = Ws_[jg * 6 + jj][nn];
                acc[jj] = fmaf(wv, f, acc[jj]);
                if (cl == 0) wsum[jj] += wv;
            }
        }
    }
    __syncthreads();
    if (cl == 0)
        #pragma unroll
        for (int jj = 0; jj < 6; ++jj) swj[jg * 6 + jj] = wsum[jj];
    __syncthreads();
    if (c < 451)
        #pragma unroll
        for (int jj = 0; jj < 6; ++jj) {
            int j = jg * 6 + jj;
            pooled[((size_t)b * Jj + j) * 451 + c] = acc[jj] / (swj[j] + 1e-5f);
        }
}

// ---------------------------------------------------------------------------
extern "C" void kernel_launch(void* const* d_in, const int* in_sizes, int n_in,
                              void* d_out, int out_size) {
    const float* V   = (const float*)d_in[0];
    const float* Wmt = (const float*)d_in[1];
    const int*   sIx = (const int*)d_in[2];
    const float* g1w = (const float*)d_in[3];  const float* g1b = (const float*)d_in[4];
    const float* g2w = (const float*)d_in[5];  const float* g2b = (const float*)d_in[6];
    const float* g3w = (const float*)d_in[7];  const float* g3b = (const float*)d_in[8];
    const float* s1w = (const float*)d_in[9];  const float* s1b = (const float*)d_in[10];
    const float* s2w = (const float*)d_in[11]; const float* s2b = (const float*)d_in[12];
    const float* s3w = (const float*)d_in[13]; const float* s3b = (const float*)d_in[14];
    const float* m1w = (const float*)d_in[15]; const float* m1b = (const float*)d_in[16];
    const float* m2w = (const float*)d_in[17]; const float* m2b = (const float*)d_in[18];
    const float* m3w = (const float*)d_in[19]; const float* m3b = (const float*)d_in[20];
    float* out = (float*)d_out;

    float* S = nullptr; cudaGetSymbolAddress((void**)&S, d_SF);
    int*  KI = nullptr; cudaGetSymbolAddress((void**)&KI, d_SI);

    float* feat   = S + OF_FEAT;
    float* PQ     = S + OF_PQ;
    float* nrm    = S + OF_NORM;
    float* pooled = S + OF_POOL;
    float* joints = S + OF_JNT;
    float* t1     = S + OF_T1;
    float* t2     = S + OF_T2;
    float* wg1 = S + OF_WG1; float* wg2 = S + OF_WG2; float* wg3 = S + OF_WG3;
    float* ws1 = S + OF_WS1; float* ws2 = S + OF_WS2; float* ws3 = S + OF_WS3;

    // dynamic smem opt-in for knn kernels
    const int SM_KC16 = (16 * 260 + 16 * 68 + 64 * 260 + 256 + 64) * 4;  // 88832
    const int SM_KC3  = (3 * 260 + 3 * 68 + 64 * 260 + 256 + 64) * 4;    // 71776
    cudaFuncSetAttribute((const void*)knn_kernel<3>,
                         cudaFuncAttributeMaxDynamicSharedMemorySize, SM_KC3);
    cudaFuncSetAttribute((const void*)knn_kernel<64>,
                         cudaFuncAttributeMaxDynamicSharedMemorySize, SM_KC16);
    cudaFuncSetAttribute((const void*)knn_kernel<128>,
                         cudaFuncAttributeMaxDynamicSharedMemorySize, SM_KC16);

    // ---- combined edge-conv weights
    prep_wc_kernel<<<(64 * 3 + 255) / 256, 256>>>(g1w, wg1, 64, 3);
    prep_wc_kernel<<<(128 * 64 + 255) / 256, 256>>>(g2w, wg2, 128, 64);
    prep_wc_kernel<<<(256 * 128 + 255) / 256, 256>>>(g3w, wg3, 256, 128);
    prep_wc_kernel<<<(256 * 451 + 255) / 256, 256>>>(s1w, ws1, 256, 451);
    prep_wc_kernel<<<(128 * 256 + 255) / 256, 256>>>(s2w, ws2, 128, 256);
    prep_wc_kernel<<<(64 * 128 + 255) / 256, 256>>>(s3w, ws3, 64, 128);

    const int M = Bb * Nn;               // 16384
    const int normBlocks = (M * 32 + 255) / 256;

    // ---- geo layer 1 (C=3 -> O=64)
    norms_kernel<<<normBlocks, 256>>>(V, 3, 3, nrm, M);
    knn_kernel<3><<<dim3(Nn / 64, Bb), 256, SM_KC3>>>(V, 3, nrm, KI);
    gemm_kernel<<<dim3(M / 64, 2), 256>>>(V, 3, wg1, g1b, 64, PQ, 128, M, 128, 3, 0);
    gathermax_kernel<<<M, 256>>>(PQ, 64, KI, KTOP, Nn, feat + 3, 451);
    copyV_kernel<<<(Bb * Nn * 3 + 255) / 256, 256>>>(V, feat);

    // ---- geo layer 2 (C=64 -> O=128)
    norms_kernel<<<normBlocks, 256>>>(feat + 3, 451, 64, nrm, M);
    knn_kernel<64><<<dim3(Nn / 64, Bb), 256, SM_KC16>>>(feat + 3, 451, nrm, KI);
    gemm_kernel<<<dim3(M / 64, 4), 256>>>(feat + 3, 451, wg2, g2b, 128, PQ, 256, M, 256, 64, 0);
    gathermax_kernel<<<M, 256>>>(PQ, 128, KI, KTOP, Nn, feat + 67, 451);

    // ---- geo layer 3 (C=128 -> O=256)
    norms_kernel<<<normBlocks, 256>>>(feat + 67, 451, 128, nrm, M);
    knn_kernel<128><<<dim3(Nn / 64, Bb), 256, SM_KC16>>>(feat + 67, 451, nrm, KI);
    gemm_kernel<<<dim3(M / 64, 8), 256>>>(feat + 67, 451, wg3, g3b, 256, PQ, 512, M, 512, 128, 0);
    gathermax_kernel<<<M, 256>>>(PQ, 256, KI, KTOP, Nn, feat + 195, 451);

    // ---- weighted pooling onto 24 joints
    pool_kernel<<<dim3(8, Bb), 256>>>(Wmt, feat, pooled);

    const int MJ = Bb * Jj;              // 96
    // ---- skeleton edge conv 1 (C=451 -> O=256)
    gemm_kernel<<<dim3(2, 8), 256>>>(pooled, 451, ws1, s1b, 256, PQ, 512, MJ, 512, 451, 0);
    gathermax_kernel<<<MJ, 256>>>(PQ, 256, sIx, 4, Jj, joints, 448);
    // ---- skeleton edge conv 2 (C=256 -> O=128)
    gemm_kernel<<<dim3(2, 4), 256>>>(joints, 448, ws2, s2b, 128, PQ, 256, MJ, 256, 256, 0);
    gathermax_kernel<<<MJ, 256>>>(PQ, 128, sIx, 4, Jj, joints + 256, 448);
    // ---- skeleton edge conv 3 (C=128 -> O=64)
    gemm_kernel<<<dim3(2, 2), 256>>>(joints + 256, 448, ws3, s3b, 64, PQ, 128, MJ, 128, 128, 0);
    gathermax_kernel<<<MJ, 256>>>(PQ, 64, sIx, 4, Jj, joints + 384, 448);

    // ---- joint MLP 448 -> 512 -> 256 -> 3
    gemm_kernel<<<dim3(2, 8), 256>>>(joints, 448, m1w, m1b, 0, t1, 512, MJ, 512, 448, 1);
    gemm_kernel<<<dim3(2, 4), 256>>>(t1, 512, m2w, m2b, 0, t2, 256, MJ, 256, 512, 1);
    gemm_kernel<<<dim3(2, 1), 256>>>(t2, 256, m3w, m3b, 0, out, 3, MJ, 3, 256, 0);
}